// round 5
// baseline (speedup 1.0000x reference)
#include <cuda_runtime.h>

// Problem constants (match reference)
#define BATCH   512
#define IN_DIM  784
#define OUT_DIM 10
#define STEPS   200
#define NSCAN   (STEPS - 1)   // 199 drive slices / scan steps
#define IHALF   (IN_DIM / 2)  // 392 = 49 batches of 8
#define CAP     22            // per-thread list capacity (mean 7.84, sd 2.78, z=5.1)

// LIF constants
#define A_M     0.995f        // 1 - DT/TAU_M
#define G_M     0.005f        // DT/TAU_M
#define A_S     0.98f         // 1 - DT/TAU_S

__device__ __forceinline__ float ldcs(const float* p) {
    float v;
    asm volatile("ld.global.cs.f32 %0, [%1];" : "=f"(v) : "l"(p));
    return v;
}

__device__ __forceinline__ void addp(unsigned long long& acc, unsigned long long w) {
    asm("add.rn.f32x2 %0, %1, %2;" : "=l"(acc) : "l"(acc), "l"(w));
}

__global__ __launch_bounds__(512, 4)
void snn_kernel(const float* __restrict__ x,     // [B, IN, STEPS]
                const float* __restrict__ w,     // [O, IN]
                float* __restrict__ out)         // [B, O]
{
    __shared__ float          wsh[IN_DIM * OUT_DIM];   // [i][o], 31360 B
    __shared__ unsigned short lists[512 * CAP];        // 22528 B; aliased by drv
    float* drv = reinterpret_cast<float*>(lists);      // [t][o], 7960 B (lists dead by then)

    const int b     = blockIdx.x;
    const int tid   = threadIdx.x;
    const int half  = tid >> 8;                  // 0 or 1: which i-half
    const int t     = tid & 255;                 // time index within half
    const int lbase = tid * CAP;                 // this thread's private list

    // Load weights into smem transposed: wsh[i*10 + o] = w[o*784 + i]
    for (int k = tid; k < IN_DIM * OUT_DIM; k += blockDim.x) {
        int i = k / OUT_DIM;
        int o = k - i * OUT_DIM;
        wsh[k] = w[o * IN_DIM + i];
    }
    __syncthreads();

    const float* xb = x + (size_t)b * IN_DIM * STEPS;

    // 5 packed f32x2 accumulators = 10 output channels
    unsigned long long acc[5] = {0ull, 0ull, 0ull, 0ull, 0ull};
    int cnt = 0;

    if (t < NSCAN) {
        const int ibase = half * IHALF;
        const float* xh = xb + (size_t)ibase * STEPS + t;

        // ---- Phase A: stream x, compact nonzero i's into private smem list ----
        #pragma unroll 1
        for (int i0 = 0; i0 < IHALF; i0 += 8) {
            float v[8];
            #pragma unroll
            for (int j = 0; j < 8; j++)
                v[j] = ldcs(xh + (size_t)(i0 + j) * STEPS);
            #pragma unroll
            for (int j = 0; j < 8; j++) {
                if (__float_as_uint(v[j]) != 0u) {        // x binary, ~2% dense
                    int i = ibase + i0 + j;
                    if (cnt < CAP) {
                        lists[lbase + cnt] = (unsigned short)(i * (OUT_DIM * 4));
                        cnt++;
                    } else {
                        // overflow fallback (P ~ 2e-7 per list): accumulate now
                        const unsigned long long* wr =
                            (const unsigned long long*)&wsh[i * OUT_DIM];
                        #pragma unroll
                        for (int p = 0; p < 5; p++) addp(acc[p], wr[p]);
                    }
                }
            }
        }

        // ---- Phase B: dense walk of private list (no divergence waste) ----
        #pragma unroll 1
        for (int k = 0; k < cnt; k++) {
            unsigned off = lists[lbase + k];
            const unsigned long long* wr =
                (const unsigned long long*)((const char*)wsh + off);
            #pragma unroll
            for (int p = 0; p < 5; p++) addp(acc[p], wr[p]);
        }
    }

    // All list reads done before drv (aliased) is written.
    __syncthreads();

    // Combine the two i-half partials through smem.
    if (half == 1 && t < NSCAN) {
        #pragma unroll
        for (int p = 0; p < 5; p++) {
            drv[t * OUT_DIM + 2 * p]     = __uint_as_float((unsigned)(acc[p] & 0xFFFFFFFFull));
            drv[t * OUT_DIM + 2 * p + 1] = __uint_as_float((unsigned)(acc[p] >> 32));
        }
    }
    __syncthreads();
    if (half == 0 && t < NSCAN) {
        #pragma unroll
        for (int p = 0; p < 5; p++) {
            drv[t * OUT_DIM + 2 * p]     += __uint_as_float((unsigned)(acc[p] & 0xFFFFFFFFull));
            drv[t * OUT_DIM + 2 * p + 1] += __uint_as_float((unsigned)(acc[p] >> 32));
        }
    }
    __syncthreads();

    // Sequential LIF scan per output neuron; record first spike time.
    if (tid < OUT_DIM) {
        const int o = tid;
        float V = 0.0f, I = 0.0f;
        int fst = 0;
        for (int tt = 0; tt < NSCAN; tt++) {
            float Vn = A_M * V + G_M * I;
            float In = A_S * I + drv[tt * OUT_DIM + o];
            if (Vn > 1.0f) { fst = tt + 1; break; }
            V = Vn;
            I = In;
        }
        out[b * OUT_DIM + o] = (fst == 0) ? (float)(STEPS - 1) : (float)fst;
    }
}

extern "C" void kernel_launch(void* const* d_in, const int* in_sizes, int n_in,
                              void* d_out, int out_size)
{
    const float* x = (const float*)d_in[0];   // [512, 784, 200]
    const float* w = (const float*)d_in[1];   // [10, 784]
    float* out = (float*)d_out;               // [512, 10]
    snn_kernel<<<BATCH, 512>>>(x, w, out);
}

// round 6
// speedup vs baseline: 5.5869x; 5.5869x over previous
#include <cuda_runtime.h>

// Problem constants (match reference)
#define BATCH   512
#define IN_DIM  784
#define OUT_DIM 10
#define STEPS   200
#define NSCAN   (STEPS - 1)        // 199 drive entries / scan steps
#define TC      32                 // time-chunk size
#define NCHUNK  ((NSCAN + TC - 1) / TC)  // 7
#define NG      16                 // i-groups (one warp each)
#define IPG     (IN_DIM / NG)      // 49 inputs per group

// LIF constants
#define A_M     0.995f             // 1 - DT/TAU_M
#define G_M     0.005f             // DT/TAU_M
#define A_S     0.98f              // 1 - DT/TAU_S

__device__ __forceinline__ float ldcs(const float* p) {
    float v;
    asm volatile("ld.global.cs.f32 %0, [%1];" : "=f"(v) : "l"(p));
    return v;
}

__device__ __forceinline__ void addp(unsigned long long& acc, unsigned long long w) {
    asm("add.rn.f32x2 %0, %1, %2;" : "=l"(acc) : "l"(acc), "l"(w));
}

__device__ __forceinline__ float lo32(unsigned long long a) {
    return __uint_as_float((unsigned)(a & 0xFFFFFFFFull));
}
__device__ __forceinline__ float hi32(unsigned long long a) {
    return __uint_as_float((unsigned)(a >> 32));
}

__global__ __launch_bounds__(512, 4)
void snn_kernel(const float* __restrict__ x,     // [B, IN, STEPS]
                const float* __restrict__ w,     // [O, IN]
                float* __restrict__ out)         // [B, O]
{
    __shared__ float wsh[IN_DIM * OUT_DIM];      // [i][o], 31360 B
    __shared__ float drvp[8][TC * OUT_DIM];      // 8 partial drives [t][o], 10240 B
    __shared__ int   done_sh;

    const int b   = blockIdx.x;
    const int tid = threadIdx.x;
    const int g   = tid >> 5;                    // warp id = i-group
    const int tl  = tid & 31;                    // t within chunk (lane)

    // Load weights into smem transposed: wsh[i*10 + o] = w[o*784 + i]
    for (int k = tid; k < IN_DIM * OUT_DIM; k += 512) {
        int i = k / OUT_DIM;
        int o = k - i * OUT_DIM;
        wsh[k] = w[o * IN_DIM + i];
    }
    if (tid == 0) done_sh = 0;
    __syncthreads();

    const float* xb = x + (size_t)b * IN_DIM * STEPS;

    // LIF state for threads 0..9 (persists across chunks)
    float V = 0.0f, I = 0.0f;
    int   fst = 0;

    for (int c = 0; c < NCHUNK; c++) {
        const int t0   = c * TC;
        const int tcur = t0 + tl;                // global drive index this lane computes

        // ---- partial drive for this chunk: warp g covers i in [g*49, g*49+49) ----
        unsigned long long acc[5] = {0ull, 0ull, 0ull, 0ull, 0ull};
        if (tcur < NSCAN) {
            const int ibase = g * IPG;
            const float* xp = xb + (size_t)ibase * STEPS + tcur;
            #pragma unroll 1
            for (int i0 = 0; i0 < IPG; i0 += 7) {    // 49 = 7 x 7
                float v[7];
                #pragma unroll
                for (int j = 0; j < 7; j++)
                    v[j] = ldcs(xp + (size_t)(i0 + j) * STEPS);
                #pragma unroll
                for (int j = 0; j < 7; j++) {
                    if (__float_as_uint(v[j]) != 0u) {   // binary, ~2% dense
                        const unsigned long long* wr =
                            (const unsigned long long*)&wsh[(ibase + i0 + j) * OUT_DIM];
                        #pragma unroll
                        for (int p = 0; p < 5; p++) addp(acc[p], wr[p]);
                    }
                }
            }
        }

        // ---- reduce 16 partials -> 8 -> 1 ----
        float* dp = &drvp[g & 7][tl * OUT_DIM];
        if (g >= 8) {
            #pragma unroll
            for (int p = 0; p < 5; p++) {
                dp[2 * p]     = lo32(acc[p]);
                dp[2 * p + 1] = hi32(acc[p]);
            }
        }
        __syncthreads();
        if (g < 8) {
            #pragma unroll
            for (int p = 0; p < 5; p++) {
                dp[2 * p]     += lo32(acc[p]);
                dp[2 * p + 1] += hi32(acc[p]);
            }
        }
        __syncthreads();
        if (tid < TC * OUT_DIM) {                // 320 threads: one (t,o) each
            float s = drvp[0][tid];
            #pragma unroll
            for (int q = 1; q < 8; q++) s += drvp[q][tid];
            drvp[0][tid] = s;
        }
        __syncthreads();

        // ---- incremental LIF scan by threads 0..9 ----
        if (tid < OUT_DIM) {
            const int o    = tid;
            const int tend = min(TC, NSCAN - t0);
            if (fst == 0) {
                for (int tt = 0; tt < tend; tt++) {
                    float Vn = A_M * V + G_M * I;
                    float In = A_S * I + drvp[0][tt * OUT_DIM + o];
                    if (Vn > 1.0f) { fst = t0 + tt + 1; break; }
                    V = Vn;
                    I = In;
                }
            }
            unsigned m = __ballot_sync(0x3FFu, fst != 0);
            if (tid == 0 && m == 0x3FFu) done_sh = 1;
        }
        __syncthreads();
        if (done_sh) break;      // all 10 neurons spiked: remaining x[b] is dead data
    }

    if (tid < OUT_DIM)
        out[b * OUT_DIM + tid] = (fst == 0) ? (float)(STEPS - 1) : (float)fst;
}

extern "C" void kernel_launch(void* const* d_in, const int* in_sizes, int n_in,
                              void* d_out, int out_size)
{
    const float* x = (const float*)d_in[0];   // [512, 784, 200]
    const float* w = (const float*)d_in[1];   // [10, 784]
    float* out = (float*)d_out;               // [512, 10]
    snn_kernel<<<BATCH, 512>>>(x, w, out);
}

// round 7
// speedup vs baseline: 6.8377x; 1.2239x over previous
#include <cuda_runtime.h>

// Problem constants (match reference)
#define BATCH   512
#define IN_DIM  784
#define OUT_DIM 10
#define STEPS   200
#define NSCAN   (STEPS - 1)              // 199 drive entries / scan steps
#define TC      32                       // time-chunk size
#define NCHUNK  ((NSCAN + TC - 1) / TC)  // 7
#define NG      16                       // i-groups (one warp each)
#define IPG     (IN_DIM / NG)            // 49 inputs per warp

// LIF constants
#define A_M     0.995f                   // 1 - DT/TAU_M
#define G_M     0.005f                   // DT/TAU_M
#define A_S     0.98f                    // 1 - DT/TAU_S

__device__ __forceinline__ float ldcs(const float* p) {
    float v;
    asm volatile("ld.global.cs.f32 %0, [%1];" : "=f"(v) : "l"(p));
    return v;
}

__global__ __launch_bounds__(512, 4)
void snn_kernel(const float* __restrict__ x,     // [B, IN, STEPS]
                const float* __restrict__ w,     // [O, IN]
                float* __restrict__ out)         // [B, O]
{
    __shared__ __align__(16) float wsh[OUT_DIM * IN_DIM]; // [o][i] (same as gmem), 31360 B
    __shared__ float drvp[8][TC * OUT_DIM];               // 8 partial drives [t][o], 10240 B
    __shared__ int   done_sh;

    const int b   = blockIdx.x;
    const int tid = threadIdx.x;
    const int g   = tid >> 5;            // warp id = i-group
    const int tl  = tid & 31;            // t within chunk (lane)

    // Weights: pure coalesced float4 copy, identical layout in smem.
    {
        const float4* w4  = (const float4*)w;
        float4*       ws4 = (float4*)wsh;
        #pragma unroll
        for (int k = tid; k < (OUT_DIM * IN_DIM) / 4; k += 512)
            ws4[k] = w4[k];
    }
    if (tid == 0) done_sh = 0;
    // NOTE: no sync here — the sync before first consume (below) covers it,
    // so weight-copy latency hides under the x-load phase.

    const float* xb = x + (size_t)b * IN_DIM * STEPS;

    // LIF state for threads 0..9 (persists across chunks)
    float V = 0.0f, I = 0.0f;
    int   fst = 0;
    const int ibase = g * IPG;

    for (int c = 0; c < NCHUNK; c++) {
        const int t0   = c * TC;
        const int tcur = t0 + tl;        // global drive index this lane computes

        // ---- Phase A: stream x[b, ibase..ibase+48, tcur] into a 49-bit mask ----
        unsigned m0 = 0u, m1 = 0u;       // bits j -> i = ibase + j (m1: j+32)
        if (tcur < NSCAN) {
            const float* xp = xb + (size_t)ibase * STEPS + tcur;
            #pragma unroll 1
            for (int i0 = 0; i0 < IPG; i0 += 7) {     // 49 = 7 x 7
                float v[7];
                #pragma unroll
                for (int j = 0; j < 7; j++)
                    v[j] = ldcs(xp + (size_t)(i0 + j) * STEPS);
                #pragma unroll
                for (int j = 0; j < 7; j++) {
                    unsigned nz = (__float_as_uint(v[j]) != 0u) ? 1u : 0u;
                    int bit = i0 + j;
                    if (bit < 32) m0 |= nz << bit;
                    else          m1 |= nz << (bit - 32);
                }
            }
        }

        if (c == 0) __syncthreads();     // uniform; weights now visible

        // ---- Phase B: dense mask walk (~1 set bit/thread on average) ----
        float acc[OUT_DIM];
        #pragma unroll
        for (int o = 0; o < OUT_DIM; o++) acc[o] = 0.0f;
        while (m0) {
            int j = __ffs(m0) - 1;
            m0 &= m0 - 1;
            const float* wr = &wsh[ibase + j];
            #pragma unroll
            for (int o = 0; o < OUT_DIM; o++) acc[o] += wr[o * IN_DIM];
        }
        while (m1) {
            int j = __ffs(m1) - 1;
            m1 &= m1 - 1;
            const float* wr = &wsh[ibase + 32 + j];
            #pragma unroll
            for (int o = 0; o < OUT_DIM; o++) acc[o] += wr[o * IN_DIM];
        }

        // ---- reduce 16 partials -> 8 -> 1 ----
        float* dp = &drvp[g & 7][tl * OUT_DIM];
        if (g >= 8) {
            #pragma unroll
            for (int o = 0; o < OUT_DIM; o++) dp[o] = acc[o];
        }
        __syncthreads();
        if (g < 8) {
            #pragma unroll
            for (int o = 0; o < OUT_DIM; o++) dp[o] += acc[o];
        }
        __syncthreads();
        if (tid < TC * OUT_DIM) {        // 320 threads: one (t,o) each
            float s = drvp[0][tid];
            #pragma unroll
            for (int q = 1; q < 8; q++) s += drvp[q][tid];
            drvp[0][tid] = s;
        }
        __syncthreads();

        // ---- incremental LIF scan by threads 0..9 ----
        if (tid < OUT_DIM) {
            const int o    = tid;
            const int tend = min(TC, NSCAN - t0);
            if (fst == 0) {
                for (int tt = 0; tt < tend; tt++) {
                    float Vn = A_M * V + G_M * I;
                    float In = A_S * I + drvp[0][tt * OUT_DIM + o];
                    if (Vn > 1.0f) { fst = t0 + tt + 1; break; }
                    V = Vn;
                    I = In;
                }
            }
            unsigned m = __ballot_sync(0x3FFu, fst != 0);
            if (tid == 0 && m == 0x3FFu) done_sh = 1;
        }
        __syncthreads();
        if (done_sh) break;              // all 10 neurons spiked: rest of x[b] is dead
    }

    if (tid < OUT_DIM)
        out[b * OUT_DIM + tid] = (fst == 0) ? (float)(STEPS - 1) : (float)fst;
}

extern "C" void kernel_launch(void* const* d_in, const int* in_sizes, int n_in,
                              void* d_out, int out_size)
{
    const float* x = (const float*)d_in[0];   // [512, 784, 200]
    const float* w = (const float*)d_in[1];   // [10, 784]
    float* out = (float*)d_out;               // [512, 10]
    snn_kernel<<<BATCH, 512>>>(x, w, out);
}